// round 14
// baseline (speedup 1.0000x reference)
#include <cuda_runtime.h>
#include <cuda_fp16.h>
#include <cuda_bf16.h>
#include <cstdint>

#define B   32
#define N   2048
#define VD  256
#define LR  64
#define EMB 256
#define ROWS (B*N)
#define EPS_DIAG 1e-6f
#define EPS_BN   1e-5f

// Scratch (device globals)
__device__ float g_W[128 * 256];      // interleaved: row c even -> W1[c/2], odd -> W2[c/2]
__device__ float g_bias[128];
__device__ __half g_P[(size_t)ROWS * LR];   // 8 MB: P[m][l] = dr_m * right[m][l]
__device__ float g_s[B * LR];
__device__ float g_feat[B * EMB];           // accumulated feat (pre-bias)

// k_main dynamic smem layout (bytes)
#define SM_AS   0
#define SM_BS   36864
#define SM_D    73728
#define SM_S    74240
#define SM_BIAS 74496
#define SMEM_MAIN 75008

__device__ __forceinline__ uint32_t pack_h2(float lo, float hi) {
    __half2 h = __floats2half2_rn(lo, hi);
    return *(uint32_t*)&h;
}

__device__ __forceinline__ void mma_f16(float c[4], const uint32_t a[4], const uint32_t b[2]) {
    asm volatile(
        "mma.sync.aligned.m16n8k16.row.col.f32.f16.f16.f32 "
        "{%0,%1,%2,%3}, {%4,%5,%6,%7}, {%8,%9}, {%0,%1,%2,%3};"
        : "+f"(c[0]), "+f"(c[1]), "+f"(c[2]), "+f"(c[3])
        : "r"(a[0]), "r"(a[1]), "r"(a[2]), "r"(a[3]), "r"(b[0]), "r"(b[1]));
}

__device__ __forceinline__ void ldsm_x4(uint32_t r[4], uint32_t addr) {
    asm volatile("ldmatrix.sync.aligned.m8n8.x4.shared.b16 {%0,%1,%2,%3}, [%4];"
        : "=r"(r[0]), "=r"(r[1]), "=r"(r[2]), "=r"(r[3]) : "r"(addr));
}

// ---------------------------------------------------------------------------
// Kernel A: weight norm + zero accumulators.  grid 128, block 256
__global__ void k_weightnorm(const float* __restrict__ U1_v, const float* __restrict__ U1_g,
                             const float* __restrict__ U1_b, const float* __restrict__ U2_v,
                             const float* __restrict__ U2_g, const float* __restrict__ U2_b)
{
    int row = blockIdx.x;
    int l = row >> 1;
    bool odd = row & 1;
    const float* v = (odd ? U2_v : U1_v) + l * VD;
    const float* g = odd ? U2_g : U1_g;
    const float* bb = odd ? U2_b : U1_b;
    int tid = threadIdx.x;

    float x = v[tid];
    float ss = x * x;
    #pragma unroll
    for (int off = 16; off >= 1; off >>= 1) ss += __shfl_xor_sync(0xffffffff, ss, off);
    __shared__ float warp_ss[8];
    __shared__ float scale_sh;
    if ((tid & 31) == 0) warp_ss[tid >> 5] = ss;
    __syncthreads();
    if (tid == 0) {
        float tot = 0.f;
        #pragma unroll
        for (int w = 0; w < 8; w++) tot += warp_ss[w];
        scale_sh = g[l] * rsqrtf(tot);
    }
    __syncthreads();
    g_W[row * 256 + tid] = x * scale_sh;
    if (tid == 0) g_bias[row] = bb[l];

    int idx = blockIdx.x * 256 + tid;
    if (idx < B * LR) g_s[idx] = 0.f;
    if (idx < B * EMB) g_feat[idx] = 0.f;
}

// ---------------------------------------------------------------------------
// Kernel C: fp16 tensor-core GEMM + fused epilogue. (61.4us-measured version)
__global__ void __launch_bounds__(256, 2) k_main(const float* __restrict__ Vmat)
{
    extern __shared__ char smem[];
    uint32_t (*As)[128][36] = (uint32_t(*)[128][36])(smem + SM_AS);
    uint32_t (*Bs)[128][36] = (uint32_t(*)[128][36])(smem + SM_BS);
    float* d_sh    = (float*)(smem + SM_D);
    float* s_sh    = (float*)(smem + SM_S);
    float* bias_sh = (float*)(smem + SM_BIAS);

    int tid = threadIdx.x;
    int lane = tid & 31, wid = tid >> 5;
    int warp_m = wid & 3, warp_n = wid >> 2;
    int qr = lane >> 2, qk = lane & 3;
    int tileRow0 = blockIdx.x * 128;
    int batch = blockIdx.x >> 4;

    if (tid < 128) { d_sh[tid] = 0.f; bias_sh[tid] = g_bias[tid]; }
    if (tid < 64) s_sh[tid] = 0.f;

    float acc[2][8][4];
    #pragma unroll
    for (int mt = 0; mt < 2; mt++)
        #pragma unroll
        for (int nt = 0; nt < 8; nt++)
            #pragma unroll
            for (int c = 0; c < 4; c++) acc[mt][nt][c] = 0.f;

    const float* Vbase = Vmat + (size_t)tileRow0 * VD;
    int lrow = tid >> 3;
    int lkq  = tid & 7;

    uint32_t sA = (uint32_t)__cvta_generic_to_shared(&As[0][0][0]);
    uint32_t sB = (uint32_t)__cvta_generic_to_shared(&Bs[0][0][0]);
    const uint32_t STAGE = 128u * 36u * 4u;
    int l8 = lane & 7, lm = lane >> 3;
    uint32_t a_base[2], b_base[4];
    #pragma unroll
    for (int mt = 0; mt < 2; mt++) {
        int row = warp_m * 32 + mt * 16 + (lm & 1) * 8 + l8;
        int kp  = (lm >> 1) * 4;
        a_base[mt] = sA + (uint32_t)(row * 36 + kp) * 4;
    }
    #pragma unroll
    for (int j = 0; j < 4; j++) {
        int c  = warp_n * 64 + (2 * j + (lm >> 1)) * 8 + l8;
        int kp = (lm & 1) * 4;
        b_base[j] = sB + (uint32_t)(c * 36 + kp) * 4;
    }

    float4 ra[4], rb[4];
    #pragma unroll
    for (int i = 0; i < 4; i++) {
        int r = i * 32 + lrow;
        ra[i] = *(const float4*)(Vbase + (size_t)r * VD + lkq * 4);
        rb[i] = *(const float4*)(g_W + r * 256 + lkq * 4);
    }

    for (int kc = 0; kc < 8; kc++) {
        int st = kc & 1;
        #pragma unroll
        for (int i = 0; i < 4; i++) {
            int r = i * 32 + lrow;
            As[st][r][lkq * 2]     = pack_h2(ra[i].x, ra[i].y);
            As[st][r][lkq * 2 + 1] = pack_h2(ra[i].z, ra[i].w);
            Bs[st][r][lkq * 2]     = pack_h2(rb[i].x, rb[i].y);
            Bs[st][r][lkq * 2 + 1] = pack_h2(rb[i].z, rb[i].w);
        }
        if (kc < 7) {
            int k0 = (kc + 1) * 32;
            #pragma unroll
            for (int i = 0; i < 4; i++) {
                int r = i * 32 + lrow;
                ra[i] = *(const float4*)(Vbase + (size_t)r * VD + k0 + lkq * 4);
                rb[i] = *(const float4*)(g_W + r * 256 + k0 + lkq * 4);
            }
        }
        __syncthreads();
        uint32_t soff = st ? STAGE : 0u;
        #pragma unroll
        for (int ks = 0; ks < 2; ks++) {
            uint32_t koff = soff + ks * 32;
            uint32_t af[2][4];
            ldsm_x4(af[0], a_base[0] + koff);
            ldsm_x4(af[1], a_base[1] + koff);
            uint32_t bf[8][2];
            #pragma unroll
            for (int j = 0; j < 4; j++) {
                uint32_t t[4];
                ldsm_x4(t, b_base[j] + koff);
                bf[2 * j][0]     = t[0];
                bf[2 * j][1]     = t[1];
                bf[2 * j + 1][0] = t[2];
                bf[2 * j + 1][1] = t[3];
            }
            #pragma unroll
            for (int mt = 0; mt < 2; mt++)
                #pragma unroll
                for (int nt = 0; nt < 8; nt++)
                    mma_f16(acc[mt][nt], af[mt], bf[nt]);
        }
    }
    __syncthreads();

    float be[8], bo[8];
    #pragma unroll
    for (int nt = 0; nt < 8; nt++) {
        int c0 = warp_n * 64 + nt * 8 + qk * 2;
        be[nt] = bias_sh[c0];
        bo[nt] = bias_sh[c0 + 1];
    }

    #pragma unroll
    for (int mt = 0; mt < 2; mt++) {
        #pragma unroll
        for (int h = 0; h < 2; h++) {
            float dpart = 0.f;
            #pragma unroll
            for (int nt = 0; nt < 8; nt++) {
                float rv = fmaxf(acc[mt][nt][h * 2]     + be[nt], 0.f);
                float lv = fmaxf(acc[mt][nt][h * 2 + 1] + bo[nt], 0.f);
                acc[mt][nt][h * 2] = rv;
                acc[mt][nt][h * 2 + 1] = lv;
                dpart = fmaf(rv, lv, dpart);
            }
            dpart += __shfl_xor_sync(0xffffffff, dpart, 1);
            dpart += __shfl_xor_sync(0xffffffff, dpart, 2);
            if (qk == 0) {
                int rl = warp_m * 32 + mt * 16 + h * 8 + qr;
                atomicAdd(&d_sh[rl], dpart);
            }
        }
    }
    __syncthreads();

    float s_t[8];
    #pragma unroll
    for (int nt = 0; nt < 8; nt++) s_t[nt] = 0.f;

    #pragma unroll
    for (int mt = 0; mt < 2; mt++) {
        #pragma unroll
        for (int h = 0; h < 2; h++) {
            int rl = warp_m * 32 + mt * 16 + h * 8 + qr;
            float dr = rsqrtf(d_sh[rl] + EPS_DIAG);
            int row = tileRow0 + rl;
            __half* pp = g_P + (size_t)row * LR + warp_n * 32;
            #pragma unroll
            for (int nt = 0; nt < 8; nt++) {
                pp[nt * 4 + qk] = __float2half(dr * acc[mt][nt][h * 2]);
                s_t[nt] = fmaf(dr, acc[mt][nt][h * 2 + 1], s_t[nt]);
            }
        }
    }
    #pragma unroll
    for (int off = 4; off <= 16; off <<= 1)
        #pragma unroll
        for (int nt = 0; nt < 8; nt++)
            s_t[nt] += __shfl_xor_sync(0xffffffff, s_t[nt], off);
    if (qr == 0) {
        #pragma unroll
        for (int nt = 0; nt < 8; nt++)
            atomicAdd(&s_sh[warp_n * 32 + nt * 4 + qk], s_t[nt]);
    }
    __syncthreads();
    if (tid < 64) atomicAdd(&g_s[batch * LR + tid], s_sh[tid]);
}

// ---------------------------------------------------------------------------
// Kernel D: c[m] = N+1 - s.P[m]; partial v = sum_m c[m]*V[m,:];
//           feat partial: pf[e] = (1/N) * sum_d v[d]*W_lin[e,d] -> atomic g_feat
// grid (4, 32), block 256.
__global__ void __launch_bounds__(256) k_final(const float* __restrict__ Vmat,
                                               const float* __restrict__ W_lin)
{
    __shared__ float s_sh[64];
    __shared__ float c_sh[512];
    __shared__ float red[4][256];
    __shared__ float vsum[256];
    int tid = threadIdx.x;
    int b = blockIdx.y;
    int m0 = blockIdx.x * 512;

    if (tid < 64) s_sh[tid] = g_s[b * LR + tid];
    __syncthreads();

    #pragma unroll
    for (int i = 0; i < 2; i++) {
        int row = b * N + m0 + tid + i * 256;
        const uint4* pp = (const uint4*)(g_P + (size_t)row * LR);
        float dot = 0.f;
        #pragma unroll
        for (int q = 0; q < 8; q++) {
            uint4 u = pp[q];
            float2 f0 = __half22float2(*(__half2*)&u.x);
            float2 f1 = __half22float2(*(__half2*)&u.y);
            float2 f2 = __half22float2(*(__half2*)&u.z);
            float2 f3 = __half22float2(*(__half2*)&u.w);
            const float* sv = &s_sh[q * 8];
            dot = fmaf(f0.x, sv[0], dot); dot = fmaf(f0.y, sv[1], dot);
            dot = fmaf(f1.x, sv[2], dot); dot = fmaf(f1.y, sv[3], dot);
            dot = fmaf(f2.x, sv[4], dot); dot = fmaf(f2.y, sv[5], dot);
            dot = fmaf(f3.x, sv[6], dot); dot = fmaf(f3.y, sv[7], dot);
        }
        c_sh[tid + i * 256] = (float)(N + 1) - dot;
    }
    __syncthreads();

    int g = tid >> 6;
    int c4 = (tid & 63) * 4;
    const float* Vp = Vmat + ((size_t)(b * N + m0 + g * 128)) * VD + c4;
    const float* cp = &c_sh[g * 128];
    float4 vac = make_float4(0.f, 0.f, 0.f, 0.f);
    #pragma unroll 8
    for (int j = 0; j < 128; j++) {
        float4 v = *(const float4*)(Vp + (size_t)j * VD);
        float cc = cp[j];
        vac.x = fmaf(cc, v.x, vac.x);
        vac.y = fmaf(cc, v.y, vac.y);
        vac.z = fmaf(cc, v.z, vac.z);
        vac.w = fmaf(cc, v.w, vac.w);
    }
    *(float4*)&red[g][c4] = vac;
    __syncthreads();

    vsum[tid] = red[0][tid] + red[1][tid] + red[2][tid] + red[3][tid];
    __syncthreads();

    // feat partial: thread e projects vsum through W_lin row e
    {
        int e = tid;
        const float4* wr = (const float4*)(W_lin + e * VD);
        const float4* vs = (const float4*)vsum;
        float acc = 0.f;
        #pragma unroll
        for (int q = 0; q < 64; q++) {
            float4 w = wr[q];
            float4 v = vs[q];
            acc = fmaf(v.x, w.x, acc);
            acc = fmaf(v.y, w.y, acc);
            acc = fmaf(v.z, w.z, acc);
            acc = fmaf(v.w, w.w, acc);
        }
        atomicAdd(&g_feat[b * EMB + e], acc * (1.0f / (float)N));
    }
}

// ---------------------------------------------------------------------------
// Kernel E: BatchNorm only. grid 8, block 1024 (warp per embed col).
__global__ void __launch_bounds__(1024) k_bn(const float* __restrict__ b_lin,
                                             const float* __restrict__ gamma,
                                             const float* __restrict__ beta,
                                             float* __restrict__ out)
{
    int tid = threadIdx.x;
    int w = tid >> 5, lane = tid & 31;
    int e = blockIdx.x * 32 + w;

    float f = g_feat[lane * EMB + e] + b_lin[e];
    float mu = f;
    #pragma unroll
    for (int off = 16; off >= 1; off >>= 1) mu += __shfl_xor_sync(0xffffffff, mu, off);
    mu *= (1.0f / 32.0f);
    float df = f - mu;
    float vv = df * df;
    #pragma unroll
    for (int off = 16; off >= 1; off >>= 1) vv += __shfl_xor_sync(0xffffffff, vv, off);
    vv *= (1.0f / 32.0f);
    out[lane * EMB + e] = df * rsqrtf(vv + EPS_BN) * gamma[e] + beta[e];
}

// ---------------------------------------------------------------------------
extern "C" void kernel_launch(void* const* d_in, const int* in_sizes, int n_in,
                              void* d_out, int out_size)
{
    const float* Vmat  = (const float*)d_in[0];
    const float* U1_v  = (const float*)d_in[1];
    const float* U1_g  = (const float*)d_in[2];
    const float* U1_b  = (const float*)d_in[3];
    const float* U2_v  = (const float*)d_in[4];
    const float* U2_g  = (const float*)d_in[5];
    const float* U2_b  = (const float*)d_in[6];
    const float* W_lin = (const float*)d_in[7];
    const float* b_lin = (const float*)d_in[8];
    const float* gamma = (const float*)d_in[9];
    const float* beta  = (const float*)d_in[10];
    float* out = (float*)d_out;

    static int smem_set = 0;
    if (!smem_set) {
        cudaFuncSetAttribute(k_main, cudaFuncAttributeMaxDynamicSharedMemorySize, SMEM_MAIN);
        smem_set = 1;
    }

    k_weightnorm<<<128, 256>>>(U1_v, U1_g, U1_b, U2_v, U2_g, U2_b);
    k_main<<<ROWS / 128, 256, SMEM_MAIN>>>(Vmat);
    k_final<<<dim3(4, B), 256>>>(Vmat, W_lin);
    k_bn<<<EMB / 32, 1024>>>(b_lin, gamma, beta, out);
}

// round 15
// speedup vs baseline: 1.0388x; 1.0388x over previous
#include <cuda_runtime.h>
#include <cuda_fp16.h>
#include <cuda_bf16.h>
#include <cstdint>

#define B   32
#define N   2048
#define VD  256
#define LR  64
#define EMB 256
#define ROWS (B*N)
#define EPS_DIAG 1e-6f
#define EPS_BN   1e-5f

// Scratch (device globals)
__device__ float g_W[128 * 256];      // interleaved: row c even -> W1[c/2], odd -> W2[c/2]
__device__ float g_bias[128];
__device__ __half g_P[(size_t)ROWS * LR];   // 8 MB: P[m][l] = dr_m * right[m][l]
__device__ float g_s[B * LR];
__device__ float g_vfinal[B * VD];
__device__ int   g_flag;              // 0 at every launch start; k_final resets

// k_main dynamic smem layout (bytes)
#define SM_AS   0
#define SM_BS   36864
#define SM_D    73728
#define SM_S    74240
#define SM_BIAS 74496
#define SMEM_MAIN 75008

__device__ __forceinline__ uint32_t pack_h2(float lo, float hi) {
    __half2 h = __floats2half2_rn(lo, hi);
    return *(uint32_t*)&h;
}

__device__ __forceinline__ void mma_f16(float c[4], const uint32_t a[4], const uint32_t b[2]) {
    asm volatile(
        "mma.sync.aligned.m16n8k16.row.col.f32.f16.f16.f32 "
        "{%0,%1,%2,%3}, {%4,%5,%6,%7}, {%8,%9}, {%0,%1,%2,%3};"
        : "+f"(c[0]), "+f"(c[1]), "+f"(c[2]), "+f"(c[3])
        : "r"(a[0]), "r"(a[1]), "r"(a[2]), "r"(a[3]), "r"(b[0]), "r"(b[1]));
}

__device__ __forceinline__ void ldsm_x4(uint32_t r[4], uint32_t addr) {
    asm volatile("ldmatrix.sync.aligned.m8n8.x4.shared.b16 {%0,%1,%2,%3}, [%4];"
        : "=r"(r[0]), "=r"(r[1]), "=r"(r[2]), "=r"(r[3]) : "r"(addr));
}

// ---------------------------------------------------------------------------
// Kernel C: weightnorm (block 0) + fp16 GEMM + fused epilogue.
// grid 512, block 256 (8 warps).
__global__ void __launch_bounds__(256, 2) k_main(const float* __restrict__ Vmat,
                                                 const float* __restrict__ U1_v,
                                                 const float* __restrict__ U1_g,
                                                 const float* __restrict__ U1_b,
                                                 const float* __restrict__ U2_v,
                                                 const float* __restrict__ U2_g,
                                                 const float* __restrict__ U2_b)
{
    extern __shared__ char smem[];
    uint32_t (*As)[128][36] = (uint32_t(*)[128][36])(smem + SM_AS);
    uint32_t (*Bs)[128][36] = (uint32_t(*)[128][36])(smem + SM_BS);
    float* d_sh    = (float*)(smem + SM_D);
    float* s_sh    = (float*)(smem + SM_S);
    float* bias_sh = (float*)(smem + SM_BIAS);

    int tid = threadIdx.x;
    int lane = tid & 31, wid = tid >> 5;
    int warp_m = wid & 3, warp_n = wid >> 2;
    int qr = lane >> 2, qk = lane & 3;
    int tileRow0 = blockIdx.x * 128;
    int batch = blockIdx.x >> 4;

    if (tid < 64) s_sh[tid] = 0.f;
    if (tid < 128) d_sh[tid] = 0.f;

    const float* Vbase = Vmat + (size_t)tileRow0 * VD;
    int lrow = tid >> 3;
    int lkq  = tid & 7;

    // ---- prefetch V chunk 0 (independent of g_W) ----
    float4 ra[4], rb[4];
    #pragma unroll
    for (int i = 0; i < 4; i++) {
        int r = i * 32 + lrow;
        ra[i] = *(const float4*)(Vbase + (size_t)r * VD + lkq * 4);
    }

    // ---- block 0: weight norm + zero accumulators; others: spin ----
    if (blockIdx.x == 0) {
        #pragma unroll 4
        for (int r = 0; r < 16; r++) {
            int row = wid * 16 + r;
            int l = row >> 1;
            bool odd = row & 1;
            const float* v = (odd ? U2_v : U1_v) + l * VD;
            float4 a = *(const float4*)(v + lane * 8);
            float4 b = *(const float4*)(v + lane * 8 + 4);
            float ss = a.x * a.x + a.y * a.y + a.z * a.z + a.w * a.w
                     + b.x * b.x + b.y * b.y + b.z * b.z + b.w * b.w;
            #pragma unroll
            for (int off = 16; off >= 1; off >>= 1)
                ss += __shfl_xor_sync(0xffffffff, ss, off);
            float scale = (odd ? U2_g : U1_g)[l] * rsqrtf(ss);
            float4 sa = make_float4(a.x * scale, a.y * scale, a.z * scale, a.w * scale);
            float4 sb = make_float4(b.x * scale, b.y * scale, b.z * scale, b.w * scale);
            *(float4*)(g_W + row * 256 + lane * 8)     = sa;
            *(float4*)(g_W + row * 256 + lane * 8 + 4) = sb;
            if (lane == 0) g_bias[row] = (odd ? U2_b : U1_b)[l];
        }
        for (int i = tid; i < B * LR; i += 256) g_s[i] = 0.f;
        for (int i = tid; i < B * VD; i += 256) g_vfinal[i] = 0.f;
        __syncthreads();
        __threadfence();
        if (tid == 0) atomicExch(&g_flag, 1);
    } else {
        if (tid == 0) {
            while (atomicAdd(&g_flag, 0) == 0) __nanosleep(64);
            __threadfence();
        }
        __syncthreads();
    }

    if (tid < 128) bias_sh[tid] = g_bias[tid];

    // ---- prefetch W chunk 0 (g_W now valid) ----
    #pragma unroll
    for (int i = 0; i < 4; i++)
        rb[i] = *(const float4*)(g_W + (i * 32 + lrow) * 256 + lkq * 4);

    float acc[2][8][4];
    #pragma unroll
    for (int mt = 0; mt < 2; mt++)
        #pragma unroll
        for (int nt = 0; nt < 8; nt++)
            #pragma unroll
            for (int c = 0; c < 4; c++) acc[mt][nt][c] = 0.f;

    uint32_t sA = (uint32_t)__cvta_generic_to_shared(&As[0][0][0]);
    uint32_t sB = (uint32_t)__cvta_generic_to_shared(&Bs[0][0][0]);
    const uint32_t STAGE = 128u * 36u * 4u;
    int l8 = lane & 7, lm = lane >> 3;
    uint32_t a_base[2], b_base[4];
    #pragma unroll
    for (int mt = 0; mt < 2; mt++) {
        int row = warp_m * 32 + mt * 16 + (lm & 1) * 8 + l8;
        int kp  = (lm >> 1) * 4;
        a_base[mt] = sA + (uint32_t)(row * 36 + kp) * 4;
    }
    #pragma unroll
    for (int j = 0; j < 4; j++) {
        int c  = warp_n * 64 + (2 * j + (lm >> 1)) * 8 + l8;
        int kp = (lm & 1) * 4;
        b_base[j] = sB + (uint32_t)(c * 36 + kp) * 4;
    }

    for (int kc = 0; kc < 8; kc++) {
        int st = kc & 1;
        #pragma unroll
        for (int i = 0; i < 4; i++) {
            int r = i * 32 + lrow;
            As[st][r][lkq * 2]     = pack_h2(ra[i].x, ra[i].y);
            As[st][r][lkq * 2 + 1] = pack_h2(ra[i].z, ra[i].w);
            Bs[st][r][lkq * 2]     = pack_h2(rb[i].x, rb[i].y);
            Bs[st][r][lkq * 2 + 1] = pack_h2(rb[i].z, rb[i].w);
        }
        if (kc < 7) {
            int k0 = (kc + 1) * 32;
            #pragma unroll
            for (int i = 0; i < 4; i++) {
                int r = i * 32 + lrow;
                ra[i] = *(const float4*)(Vbase + (size_t)r * VD + k0 + lkq * 4);
                rb[i] = *(const float4*)(g_W + r * 256 + k0 + lkq * 4);
            }
        }
        __syncthreads();
        uint32_t soff = st ? STAGE : 0u;
        #pragma unroll
        for (int ks = 0; ks < 2; ks++) {
            uint32_t koff = soff + ks * 32;
            uint32_t af[2][4];
            ldsm_x4(af[0], a_base[0] + koff);
            ldsm_x4(af[1], a_base[1] + koff);
            uint32_t bf[8][2];
            #pragma unroll
            for (int j = 0; j < 4; j++) {
                uint32_t t[4];
                ldsm_x4(t, b_base[j] + koff);
                bf[2 * j][0]     = t[0];
                bf[2 * j][1]     = t[1];
                bf[2 * j + 1][0] = t[2];
                bf[2 * j + 1][1] = t[3];
            }
            #pragma unroll
            for (int mt = 0; mt < 2; mt++)
                #pragma unroll
                for (int nt = 0; nt < 8; nt++)
                    mma_f16(acc[mt][nt], af[mt], bf[nt]);
        }
    }
    __syncthreads();

    // ---- epilogue (R13-identical) ----
    float be[8], bo[8];
    #pragma unroll
    for (int nt = 0; nt < 8; nt++) {
        int c0 = warp_n * 64 + nt * 8 + qk * 2;
        be[nt] = bias_sh[c0];
        bo[nt] = bias_sh[c0 + 1];
    }

    #pragma unroll
    for (int mt = 0; mt < 2; mt++) {
        #pragma unroll
        for (int h = 0; h < 2; h++) {
            float dpart = 0.f;
            #pragma unroll
            for (int nt = 0; nt < 8; nt++) {
                float rv = fmaxf(acc[mt][nt][h * 2]     + be[nt], 0.f);
                float lv = fmaxf(acc[mt][nt][h * 2 + 1] + bo[nt], 0.f);
                acc[mt][nt][h * 2] = rv;
                acc[mt][nt][h * 2 + 1] = lv;
                dpart = fmaf(rv, lv, dpart);
            }
            dpart += __shfl_xor_sync(0xffffffff, dpart, 1);
            dpart += __shfl_xor_sync(0xffffffff, dpart, 2);
            if (qk == 0) {
                int rl = warp_m * 32 + mt * 16 + h * 8 + qr;
                atomicAdd(&d_sh[rl], dpart);
            }
        }
    }
    __syncthreads();

    float s_t[8];
    #pragma unroll
    for (int nt = 0; nt < 8; nt++) s_t[nt] = 0.f;

    #pragma unroll
    for (int mt = 0; mt < 2; mt++) {
        #pragma unroll
        for (int h = 0; h < 2; h++) {
            int rl = warp_m * 32 + mt * 16 + h * 8 + qr;
            float dr = rsqrtf(d_sh[rl] + EPS_DIAG);
            int row = tileRow0 + rl;
            __half* pp = g_P + (size_t)row * LR + warp_n * 32;
            #pragma unroll
            for (int nt = 0; nt < 8; nt++) {
                pp[nt * 4 + qk] = __float2half(dr * acc[mt][nt][h * 2]);
                s_t[nt] = fmaf(dr, acc[mt][nt][h * 2 + 1], s_t[nt]);
            }
        }
    }
    #pragma unroll
    for (int off = 4; off <= 16; off <<= 1)
        #pragma unroll
        for (int nt = 0; nt < 8; nt++)
            s_t[nt] += __shfl_xor_sync(0xffffffff, s_t[nt], off);
    if (qr == 0) {
        #pragma unroll
        for (int nt = 0; nt < 8; nt++)
            atomicAdd(&s_sh[warp_n * 32 + nt * 4 + qk], s_t[nt]);
    }
    __syncthreads();
    if (tid < 64) atomicAdd(&g_s[batch * LR + tid], s_sh[tid]);
}

// ---------------------------------------------------------------------------
// Kernel D: c[m] = N+1 - s.P[m]; v_final += (1/N)*c[m]*Vmat[m,:]
// grid (4, 32), block 256. (61.4us-measured; + flag reset)
__global__ void __launch_bounds__(256) k_final(const float* __restrict__ Vmat)
{
    __shared__ float s_sh[64];
    __shared__ float c_sh[512];
    __shared__ float red[4][256];
    int tid = threadIdx.x;
    int b = blockIdx.y;
    int m0 = blockIdx.x * 512;

    if (blockIdx.x == 0 && b == 0 && tid == 0) g_flag = 0;   // reset for next replay

    if (tid < 64) s_sh[tid] = g_s[b * LR + tid];
    __syncthreads();

    #pragma unroll
    for (int i = 0; i < 2; i++) {
        int row = b * N + m0 + tid + i * 256;
        const uint4* pp = (const uint4*)(g_P + (size_t)row * LR);
        float dot = 0.f;
        #pragma unroll
        for (int q = 0; q < 8; q++) {
            uint4 u = pp[q];
            float2 f0 = __half22float2(*(__half2*)&u.x);
            float2 f1 = __half22float2(*(__half2*)&u.y);
            float2 f2 = __half22float2(*(__half2*)&u.z);
            float2 f3 = __half22float2(*(__half2*)&u.w);
            const float* sv = &s_sh[q * 8];
            dot = fmaf(f0.x, sv[0], dot); dot = fmaf(f0.y, sv[1], dot);
            dot = fmaf(f1.x, sv[2], dot); dot = fmaf(f1.y, sv[3], dot);
            dot = fmaf(f2.x, sv[4], dot); dot = fmaf(f2.y, sv[5], dot);
            dot = fmaf(f3.x, sv[6], dot); dot = fmaf(f3.y, sv[7], dot);
        }
        c_sh[tid + i * 256] = (float)(N + 1) - dot;
    }
    __syncthreads();

    int g = tid >> 6;
    int c4 = (tid & 63) * 4;
    const float* Vp = Vmat + ((size_t)(b * N + m0 + g * 128)) * VD + c4;
    const float* cp = &c_sh[g * 128];
    float4 vac = make_float4(0.f, 0.f, 0.f, 0.f);
    #pragma unroll 8
    for (int j = 0; j < 128; j++) {
        float4 v = *(const float4*)(Vp + (size_t)j * VD);
        float cc = cp[j];
        vac.x = fmaf(cc, v.x, vac.x);
        vac.y = fmaf(cc, v.y, vac.y);
        vac.z = fmaf(cc, v.z, vac.z);
        vac.w = fmaf(cc, v.w, vac.w);
    }
    *(float4*)&red[g][c4] = vac;
    __syncthreads();

    float sum = red[0][tid] + red[1][tid] + red[2][tid] + red[3][tid];
    atomicAdd(&g_vfinal[b * VD + tid], sum * (1.0f / (float)N));
}

// ---------------------------------------------------------------------------
// Kernel E: feat = v_final @ W_lin^T + b_lin; BatchNorm over B (biased var).
// grid 256, block 128. (61.4us-measured version)
__global__ void __launch_bounds__(128) k_bn(const float* __restrict__ W_lin,
                                            const float* __restrict__ b_lin,
                                            const float* __restrict__ gamma,
                                            const float* __restrict__ beta,
                                            float* __restrict__ out)
{
    int e = blockIdx.x;
    int tid = threadIdx.x;
    __shared__ float4 w_sh[64];
    __shared__ float feats[32];

    if (tid < 64) w_sh[tid] = ((const float4*)(W_lin + e * VD))[tid];
    __syncthreads();

    int bat = tid >> 2;
    int q0  = tid & 3;
    const float4* vr = (const float4*)(g_vfinal + bat * VD);
    float dot = 0.f;
    #pragma unroll
    for (int q = 0; q < 16; q++) {
        float4 v = vr[q * 4 + q0];
        float4 w = w_sh[q * 4 + q0];
        dot = fmaf(v.x, w.x, dot);
        dot = fmaf(v.y, w.y, dot);
        dot = fmaf(v.z, w.z, dot);
        dot = fmaf(v.w, w.w, dot);
    }
    dot += __shfl_xor_sync(0xffffffff, dot, 1);
    dot += __shfl_xor_sync(0xffffffff, dot, 2);
    if (q0 == 0) feats[bat] = dot + b_lin[e];
    __syncthreads();

    if (tid < 32) {
        float f = feats[tid];
        float mu = f;
        #pragma unroll
        for (int off = 16; off >= 1; off >>= 1) mu += __shfl_xor_sync(0xffffffff, mu, off);
        mu *= (1.0f / 32.0f);
        float df = f - mu;
        float vv = df * df;
        #pragma unroll
        for (int off = 16; off >= 1; off >>= 1) vv += __shfl_xor_sync(0xffffffff, vv, off);
        vv *= (1.0f / 32.0f);
        out[tid * EMB + e] = df * rsqrtf(vv + EPS_BN) * gamma[e] + beta[e];
    }
}

// ---------------------------------------------------------------------------
extern "C" void kernel_launch(void* const* d_in, const int* in_sizes, int n_in,
                              void* d_out, int out_size)
{
    const float* Vmat  = (const float*)d_in[0];
    const float* U1_v  = (const float*)d_in[1];
    const float* U1_g  = (const float*)d_in[2];
    const float* U1_b  = (const float*)d_in[3];
    const float* U2_v  = (const float*)d_in[4];
    const float* U2_g  = (const float*)d_in[5];
    const float* U2_b  = (const float*)d_in[6];
    const float* W_lin = (const float*)d_in[7];
    const float* b_lin = (const float*)d_in[8];
    const float* gamma = (const float*)d_in[9];
    const float* beta  = (const float*)d_in[10];
    float* out = (float*)d_out;

    static int smem_set = 0;
    if (!smem_set) {
        cudaFuncSetAttribute(k_main, cudaFuncAttributeMaxDynamicSharedMemorySize, SMEM_MAIN);
        smem_set = 1;
    }

    k_main<<<ROWS / 128, 256, SMEM_MAIN>>>(Vmat, U1_v, U1_g, U1_b, U2_v, U2_g, U2_b);
    k_final<<<dim3(4, B), 256>>>(Vmat);
    k_bn<<<EMB, 128>>>(W_lin, b_lin, gamma, beta, out);
}

// round 17
// speedup vs baseline: 1.1427x; 1.1000x over previous
#include <cuda_runtime.h>
#include <cuda_fp16.h>
#include <cuda_bf16.h>
#include <cstdint>

#define B   32
#define N   2048
#define VD  256
#define LR  64
#define EMB 256
#define ROWS (B*N)
#define EPS_DIAG 1e-6f
#define EPS_BN   1e-5f

// Scratch (device globals)
__device__ uint32_t g_Wh[128 * 128];  // fp16 kpairs: row c, kpair q -> cols 2q,2q+1
__device__ float g_bias[128];
__device__ __half g_P[(size_t)ROWS * LR];   // 8 MB: P[m][l] = dr_m * right[m][l]
__device__ float g_s[B * LR];
__device__ float g_vfinal[B * VD];

// k_main dynamic smem layout (bytes)
#define SM_AS   0            // u32[2][128][36] A stages          (36864)
#define SM_W    36864        // u32[128][132]   W resident (fp16) (67584)
#define SM_D    104448       // float[128]
#define SM_S    104960       // float[64]
#define SM_BIAS 105216       // float[128]
#define SMEM_MAIN 105728

__device__ __forceinline__ uint32_t pack_h2(float lo, float hi) {
    __half2 h = __floats2half2_rn(lo, hi);
    return *(uint32_t*)&h;
}

__device__ __forceinline__ void mma_f16(float c[4], const uint32_t a[4], const uint32_t b[2]) {
    asm volatile(
        "mma.sync.aligned.m16n8k16.row.col.f32.f16.f16.f32 "
        "{%0,%1,%2,%3}, {%4,%5,%6,%7}, {%8,%9}, {%0,%1,%2,%3};"
        : "+f"(c[0]), "+f"(c[1]), "+f"(c[2]), "+f"(c[3])
        : "r"(a[0]), "r"(a[1]), "r"(a[2]), "r"(a[3]), "r"(b[0]), "r"(b[1]));
}

__device__ __forceinline__ void ldsm_x4(uint32_t r[4], uint32_t addr) {
    asm volatile("ldmatrix.sync.aligned.m8n8.x4.shared.b16 {%0,%1,%2,%3}, [%4];"
        : "=r"(r[0]), "=r"(r[1]), "=r"(r[2]), "=r"(r[3]) : "r"(addr));
}

// ---------------------------------------------------------------------------
// Kernel A: weight norm (emits fp16 kpairs) + zero accumulators. grid 128, block 256
__global__ void k_weightnorm(const float* __restrict__ U1_v, const float* __restrict__ U1_g,
                             const float* __restrict__ U1_b, const float* __restrict__ U2_v,
                             const float* __restrict__ U2_g, const float* __restrict__ U2_b)
{
    int row = blockIdx.x;
    int l = row >> 1;
    bool odd = row & 1;
    const float* v = (odd ? U2_v : U1_v) + l * VD;
    const float* g = odd ? U2_g : U1_g;
    const float* bb = odd ? U2_b : U1_b;
    int tid = threadIdx.x;

    float x = v[tid];
    float ss = x * x;
    #pragma unroll
    for (int off = 16; off >= 1; off >>= 1) ss += __shfl_xor_sync(0xffffffff, ss, off);
    __shared__ float warp_ss[8];
    __shared__ float scale_sh;
    if ((tid & 31) == 0) warp_ss[tid >> 5] = ss;
    __syncthreads();
    if (tid == 0) {
        float tot = 0.f;
        #pragma unroll
        for (int w = 0; w < 8; w++) tot += warp_ss[w];
        scale_sh = g[l] * rsqrtf(tot);
    }
    __syncthreads();
    float val = x * scale_sh;
    float val_hi = __shfl_down_sync(0xffffffff, val, 1);
    if ((tid & 1) == 0) g_Wh[row * 128 + (tid >> 1)] = pack_h2(val, val_hi);
    if (tid == 0) g_bias[row] = bb[l];

    int idx = blockIdx.x * 256 + tid;
    if (idx < B * LR) g_s[idx] = 0.f;
    if (idx < B * VD) g_vfinal[idx] = 0.f;
}

// ---------------------------------------------------------------------------
// Kernel C: fp16 GEMM with resident W + 2-deep A prefetch + fused epilogue.
// grid 512 (128-row tiles), block 256 (8 warps: 4 m x 2 n), occ 2.
__global__ void __launch_bounds__(256, 2) k_main(const float* __restrict__ Vmat)
{
    extern __shared__ char smem[];
    uint32_t (*As)[128][36] = (uint32_t(*)[128][36])(smem + SM_AS);
    uint32_t* Ws   = (uint32_t*)(smem + SM_W);
    float* d_sh    = (float*)(smem + SM_D);
    float* s_sh    = (float*)(smem + SM_S);
    float* bias_sh = (float*)(smem + SM_BIAS);

    int tid = threadIdx.x;
    int lane = tid & 31, wid = tid >> 5;
    int warp_m = wid & 3, warp_n = wid >> 2;
    int qr = lane >> 2, qk = lane & 3;
    int tileRow0 = blockIdx.x * 128;
    int batch = blockIdx.x >> 4;

    if (tid < 128) { d_sh[tid] = 0.f; bias_sh[tid] = g_bias[tid]; }
    if (tid < 64) s_sh[tid] = 0.f;

    const float* Vbase = Vmat + (size_t)tileRow0 * VD;
    int lrow = tid >> 3;
    int lkq  = tid & 7;

    // ---- A prefetch 2 chunks deep ----
    float4 ra0[4], ra1[4];
    #pragma unroll
    for (int i = 0; i < 4; i++) {
        int r = i * 32 + lrow;
        ra0[i] = *(const float4*)(Vbase + (size_t)r * VD + lkq * 4);
        ra1[i] = *(const float4*)(Vbase + (size_t)r * VD + 32 + lkq * 4);
    }

    // ---- copy W (fp16 kpairs) into resident smem, padded stride 132 ----
    {
        const uint4* src = (const uint4*)g_Wh;
        #pragma unroll
        for (int i = 0; i < 16; i++) {
            int idx = tid + i * 256;          // 0..4095
            int r = idx >> 5, q = idx & 31;   // row, uint4-slot
            *(uint4*)&Ws[r * 132 + q * 4] = src[idx];
        }
    }

    float acc[2][8][4];
    #pragma unroll
    for (int mt = 0; mt < 2; mt++)
        #pragma unroll
        for (int nt = 0; nt < 8; nt++)
            #pragma unroll
            for (int c = 0; c < 4; c++) acc[mt][nt][c] = 0.f;

    uint32_t sA = (uint32_t)__cvta_generic_to_shared(&As[0][0][0]);
    uint32_t sW = (uint32_t)__cvta_generic_to_shared(Ws);
    const uint32_t STAGE = 128u * 36u * 4u;
    int l8 = lane & 7, lm = lane >> 3;
    uint32_t a_base[2], b_base[4];
    #pragma unroll
    for (int mt = 0; mt < 2; mt++) {
        int row = warp_m * 32 + mt * 16 + (lm & 1) * 8 + l8;
        a_base[mt] = sA + (uint32_t)(row * 36 + (lm >> 1) * 4) * 4;
    }
    #pragma unroll
    for (int j = 0; j < 4; j++) {
        int c = warp_n * 64 + (2 * j + (lm >> 1)) * 8 + l8;
        b_base[j] = sW + (uint32_t)(c * 132 + (lm & 1) * 4) * 4;
    }

    for (int kc = 0; kc < 8; kc++) {
        int st = kc & 1;
        #pragma unroll
        for (int i = 0; i < 4; i++) {
            int r = i * 32 + lrow;
            As[st][r][lkq * 2]     = pack_h2(ra0[i].x, ra0[i].y);
            As[st][r][lkq * 2 + 1] = pack_h2(ra0[i].z, ra0[i].w);
        }
        #pragma unroll
        for (int i = 0; i < 4; i++) ra0[i] = ra1[i];
        if (kc < 6) {
            int k0 = (kc + 2) * 32;
            #pragma unroll
            for (int i = 0; i < 4; i++) {
                int r = i * 32 + lrow;
                ra1[i] = *(const float4*)(Vbase + (size_t)r * VD + k0 + lkq * 4);
            }
        }
        __syncthreads();
        uint32_t soff = st ? STAGE : 0u;
        #pragma unroll
        for (int ks = 0; ks < 2; ks++) {
            uint32_t a_koff = soff + ks * 32;
            uint32_t w_koff = (uint32_t)(kc * 16 + ks * 8) * 4;
            uint32_t af[2][4];
            ldsm_x4(af[0], a_base[0] + a_koff);
            ldsm_x4(af[1], a_base[1] + a_koff);
            uint32_t bf[8][2];
            #pragma unroll
            for (int j = 0; j < 4; j++) {
                uint32_t t[4];
                ldsm_x4(t, b_base[j] + w_koff);
                bf[2 * j][0]     = t[0];
                bf[2 * j][1]     = t[1];
                bf[2 * j + 1][0] = t[2];
                bf[2 * j + 1][1] = t[3];
            }
            #pragma unroll
            for (int mt = 0; mt < 2; mt++)
                #pragma unroll
                for (int nt = 0; nt < 8; nt++)
                    mma_f16(acc[mt][nt], af[mt], bf[nt]);
        }
    }
    __syncthreads();

    // ---- epilogue (R13-identical) ----
    float be[8], bo[8];
    #pragma unroll
    for (int nt = 0; nt < 8; nt++) {
        int c0 = warp_n * 64 + nt * 8 + qk * 2;
        be[nt] = bias_sh[c0];
        bo[nt] = bias_sh[c0 + 1];
    }

    #pragma unroll
    for (int mt = 0; mt < 2; mt++) {
        #pragma unroll
        for (int h = 0; h < 2; h++) {
            float dpart = 0.f;
            #pragma unroll
            for (int nt = 0; nt < 8; nt++) {
                float rv = fmaxf(acc[mt][nt][h * 2]     + be[nt], 0.f);
                float lv = fmaxf(acc[mt][nt][h * 2 + 1] + bo[nt], 0.f);
                acc[mt][nt][h * 2] = rv;
                acc[mt][nt][h * 2 + 1] = lv;
                dpart = fmaf(rv, lv, dpart);
            }
            dpart += __shfl_xor_sync(0xffffffff, dpart, 1);
            dpart += __shfl_xor_sync(0xffffffff, dpart, 2);
            if (qk == 0) {
                int rl = warp_m * 32 + mt * 16 + h * 8 + qr;
                atomicAdd(&d_sh[rl], dpart);
            }
        }
    }
    __syncthreads();

    float s_t[8];
    #pragma unroll
    for (int nt = 0; nt < 8; nt++) s_t[nt] = 0.f;

    #pragma unroll
    for (int mt = 0; mt < 2; mt++) {
        #pragma unroll
        for (int h = 0; h < 2; h++) {
            int rl = warp_m * 32 + mt * 16 + h * 8 + qr;
            float dr = rsqrtf(d_sh[rl] + EPS_DIAG);
            int row = tileRow0 + rl;
            __half* pp = g_P + (size_t)row * LR + warp_n * 32;
            #pragma unroll
            for (int nt = 0; nt < 8; nt++) {
                pp[nt * 4 + qk] = __float2half(dr * acc[mt][nt][h * 2]);
                s_t[nt] = fmaf(dr, acc[mt][nt][h * 2 + 1], s_t[nt]);
            }
        }
    }
    #pragma unroll
    for (int off = 4; off <= 16; off <<= 1)
        #pragma unroll
        for (int nt = 0; nt < 8; nt++)
            s_t[nt] += __shfl_xor_sync(0xffffffff, s_t[nt], off);
    if (qr == 0) {
        #pragma unroll
        for (int nt = 0; nt < 8; nt++)
            atomicAdd(&s_sh[warp_n * 32 + nt * 4 + qk], s_t[nt]);
    }
    __syncthreads();
    if (tid < 64) atomicAdd(&g_s[batch * LR + tid], s_sh[tid]);
}

// ---------------------------------------------------------------------------
// Kernel D: c[m] = N+1 - s.P[m]; v_final += (1/N)*c[m]*Vmat[m,:]
// grid (4, 32), block 256. (61.4us-measured version)
__global__ void __launch_bounds__(256) k_final(const float* __restrict__ Vmat)
{
    __shared__ float s_sh[64];
    __shared__ float c_sh[512];
    __shared__ float red[4][256];
    int tid = threadIdx.x;
    int b = blockIdx.y;
    int m0 = blockIdx.x * 512;

    if (tid < 64) s_sh[tid] = g_s[b * LR + tid];
    __syncthreads();

    #pragma unroll
    for (int i = 0; i < 2; i++) {
        int row = b * N + m0 + tid + i * 256;
        const uint4* pp = (const uint4*)(g_P + (size_t)row * LR);
        float dot = 0.f;
        #pragma unroll
        for (int q = 0; q < 8; q++) {
            uint4 u = pp[q];
            float2 f0 = __half22float2(*(__half2*)&u.x);
            float2 f1 = __half22float2(*(__half2*)&u.y);
            float2 f2 = __half22float2(*(__half2*)&u.z);
            float2 f3 = __half22float2(*(__half2*)&u.w);
            const float* sv = &s_sh[q * 8];
            dot = fmaf(f0.x, sv[0], dot); dot = fmaf(f0.y, sv[1], dot);
            dot = fmaf(f1.x, sv[2], dot); dot = fmaf(f1.y, sv[3], dot);
            dot = fmaf(f2.x, sv[4], dot); dot = fmaf(f2.y, sv[5], dot);
            dot = fmaf(f3.x, sv[6], dot); dot = fmaf(f3.y, sv[7], dot);
        }
        c_sh[tid + i * 256] = (float)(N + 1) - dot;
    }
    __syncthreads();

    int g = tid >> 6;
    int c4 = (tid & 63) * 4;
    const float* Vp = Vmat + ((size_t)(b * N + m0 + g * 128)) * VD + c4;
    const float* cp = &c_sh[g * 128];
    float4 vac = make_float4(0.f, 0.f, 0.f, 0.f);
    #pragma unroll 8
    for (int j = 0; j < 128; j++) {
        float4 v = *(const float4*)(Vp + (size_t)j * VD);
        float cc = cp[j];
        vac.x = fmaf(cc, v.x, vac.x);
        vac.y = fmaf(cc, v.y, vac.y);
        vac.z = fmaf(cc, v.z, vac.z);
        vac.w = fmaf(cc, v.w, vac.w);
    }
    *(float4*)&red[g][c4] = vac;
    __syncthreads();

    float sum = red[0][tid] + red[1][tid] + red[2][tid] + red[3][tid];
    atomicAdd(&g_vfinal[b * VD + tid], sum * (1.0f / (float)N));
}

// ---------------------------------------------------------------------------
// Kernel E: feat = v_final @ W_lin^T + b_lin; BatchNorm over B (biased var).
// grid 256, block 128. (61.4us-measured version)
__global__ void __launch_bounds__(128) k_bn(const float* __restrict__ W_lin,
                                            const float* __restrict__ b_lin,
                                            const float* __restrict__ gamma,
                                            const float* __restrict__ beta,
                                            float* __restrict__ out)
{
    int e = blockIdx.x;
    int tid = threadIdx.x;
    __shared__ float4 w_sh[64];
    __shared__ float feats[32];

    if (tid < 64) w_sh[tid] = ((const float4*)(W_lin + e * VD))[tid];
    __syncthreads();

    int bat = tid >> 2;
    int q0  = tid & 3;
    const float4* vr = (const float4*)(g_vfinal + bat * VD);
    float dot = 0.f;
    #pragma unroll
    for (int q = 0; q < 16; q++) {
        float4 v = vr[q * 4 + q0];
        float4 w = w_sh[q * 4 + q0];
        dot = fmaf(v.x, w.x, dot);
        dot = fmaf(v.y, w.y, dot);
        dot = fmaf(v.z, w.z, dot);
        dot = fmaf(v.w, w.w, dot);
    }
    dot += __shfl_xor_sync(0xffffffff, dot, 1);
    dot += __shfl_xor_sync(0xffffffff, dot, 2);
    if (q0 == 0) feats[bat] = dot + b_lin[e];
    __syncthreads();

    if (tid < 32) {
        float f = feats[tid];
        float mu = f;
        #pragma unroll
        for (int off = 16; off >= 1; off >>= 1) mu += __shfl_xor_sync(0xffffffff, mu, off);
        mu *= (1.0f / 32.0f);
        float df = f - mu;
        float vv = df * df;
        #pragma unroll
        for (int off = 16; off >= 1; off >>= 1) vv += __shfl_xor_sync(0xffffffff, vv, off);
        vv *= (1.0f / 32.0f);
        out[tid * EMB + e] = df * rsqrtf(vv + EPS_BN) * gamma[e] + beta[e];
    }
}

// ---------------------------------------------------------------------------
extern "C" void kernel_launch(void* const* d_in, const int* in_sizes, int n_in,
                              void* d_out, int out_size)
{
    const float* Vmat  = (const float*)d_in[0];
    const float* U1_v  = (const float*)d_in[1];
    const float* U1_g  = (const float*)d_in[2];
    const float* U1_b  = (const float*)d_in[3];
    const float* U2_v  = (const float*)d_in[4];
    const float* U2_g  = (const float*)d_in[5];
    const float* U2_b  = (const float*)d_in[6];
    const float* W_lin = (const float*)d_in[7];
    const float* b_lin = (const float*)d_in[8];
    const float* gamma = (const float*)d_in[9];
    const float* beta  = (const float*)d_in[10];
    float* out = (float*)d_out;

    static int smem_set = 0;
    if (!smem_set) {
        cudaFuncSetAttribute(k_main, cudaFuncAttributeMaxDynamicSharedMemorySize, SMEM_MAIN);
        smem_set = 1;
    }

    k_weightnorm<<<128, 256>>>(U1_v, U1_g, U1_b, U2_v, U2_g, U2_b);
    k_main<<<ROWS / 128, 256, SMEM_MAIN>>>(Vmat);
    k_final<<<dim3(4, B), 256>>>(Vmat);
    k_bn<<<EMB, 128>>>(W_lin, b_lin, gamma, beta, out);
}